// round 3
// baseline (speedup 1.0000x reference)
#include <cuda_runtime.h>
#include <math.h>

#define FULL 0xFFFFFFFFu

// ---------------- scratch (device globals; no allocation allowed) -------------
__device__ float g_ada[2 * 256];                 // [B, 2C] scale|shift
__device__ float g_q[2 * 4 * 64 * 64 * 32];      // [B,n,H,W,d]
__device__ float g_k[2 * 4 * 64 * 64 * 32];
__device__ float g_v[2 * 4 * 64 * 64 * 32];
__device__ float g_att[2 * 64 * 64 * 128];       // [B,H,W,C]

__device__ __forceinline__ int nb_start(int i) {
    int s = i - 3;
    s = s < 0 ? 0 : s;
    return s > 57 ? 57 : s;   // L-K = 64-7
}

// ---------------- kernel A: sinusoidal emb + silu + adaLN MLP -----------------
__global__ void adaln_kernel(const int* __restrict__ t,
                             const float* __restrict__ ln_w,
                             const float* __restrict__ ln_b) {
    __shared__ float s_silu[128];
    const int b = blockIdx.x;
    const int tid = threadIdx.x;
    const float tf = (float)t[b] * 40.0f;              // t/100*4000
    if (tid < 64) {
        float f = __expf(-(float)tid * (9.210340371976184f / 63.0f));
        float e = tf * f;
        float se = sinf(e), ce = cosf(e);
        s_silu[tid]      = se / (1.0f + __expf(-se));
        s_silu[tid + 64] = ce / (1.0f + __expf(-ce));
    }
    __syncthreads();
    const int j = tid;                                  // 0..255
    float acc = ln_b[j];
#pragma unroll 16
    for (int k = 0; k < 128; k++) acc += s_silu[k] * ln_w[k * 256 + j];
    g_ada[b * 256 + j] = acc;
}

// ---------------- kernel B: fused LayerNorm + qkv GEMM ------------------------
// grid(128,6), block(128). tile 64x64, thread 4x8, full K in smem, one sync.
// LN computed in-block (redundantly per n-tile; cheap).
__global__ void qkv_gemm(const float* __restrict__ x,
                         const float* __restrict__ W,
                         const float* __restrict__ bias) {
    __shared__ float sa[64 * 132];       // LN'd activations [m][k], pad 132
    __shared__ float sb[128 * 64];       // weights [k][n]
    const int tid = threadIdx.x;
    const int m0 = blockIdx.x * 64, n0 = blockIdx.y * 64;
    const int b = m0 >> 12;              // 64 | 4096 -> uniform per block

    const int warp = tid >> 5, lane = tid & 31;

    // --- LN: each warp handles 16 rows ---
    const float4 sc4 = *(const float4*)(g_ada + b * 256 + lane * 4);
    const float4 sh4 = *(const float4*)(g_ada + b * 256 + 128 + lane * 4);
#pragma unroll 4
    for (int rr = 0; rr < 16; rr++) {
        const int r = warp * 16 + rr;
        const float4 xv = *(const float4*)(x + (m0 + r) * 128 + lane * 4);
        float sum = xv.x + xv.y + xv.z + xv.w;
        float sq  = xv.x * xv.x + xv.y * xv.y + xv.z * xv.z + xv.w * xv.w;
#pragma unroll
        for (int o = 16; o; o >>= 1) {
            sum += __shfl_xor_sync(FULL, sum, o);
            sq  += __shfl_xor_sync(FULL, sq, o);
        }
        const float mean = sum * (1.0f / 128.0f);
        const float var  = sq * (1.0f / 128.0f) - mean * mean;
        const float rstd = rsqrtf(var + 1e-5f);
        float4 yv;
        yv.x = (xv.x - mean) * rstd * (1.0f + sc4.x) + sh4.x;
        yv.y = (xv.y - mean) * rstd * (1.0f + sc4.y) + sh4.y;
        yv.z = (xv.z - mean) * rstd * (1.0f + sc4.z) + sh4.z;
        yv.w = (xv.w - mean) * rstd * (1.0f + sc4.w) + sh4.w;
        *(float4*)(sa + r * 132 + lane * 4) = yv;
    }

#pragma unroll
    for (int r = 0; r < 16; r++) {
        const int id = tid + r * 128;
        const int kk = id >> 4, j4 = id & 15;
        *(float4*)(sb + kk * 64 + j4 * 4) =
            *(const float4*)(W + kk * 384 + n0 + j4 * 4);
    }
    __syncthreads();

    const int rg = lane >> 3, cg = lane & 7;
    const int rowb = warp * 16 + rg * 4;

    float acc[4][8];
#pragma unroll
    for (int i = 0; i < 4; i++)
#pragma unroll
        for (int c = 0; c < 8; c++) acc[i][c] = 0.0f;

#pragma unroll 8
    for (int kk = 0; kk < 128; kk++) {
        const float a0 = sa[(rowb + 0) * 132 + kk];
        const float a1 = sa[(rowb + 1) * 132 + kk];
        const float a2 = sa[(rowb + 2) * 132 + kk];
        const float a3 = sa[(rowb + 3) * 132 + kk];
        const float4 b0 = *(const float4*)(sb + kk * 64 + cg * 8);
        const float4 b1 = *(const float4*)(sb + kk * 64 + cg * 8 + 4);
        acc[0][0] += a0 * b0.x; acc[0][1] += a0 * b0.y; acc[0][2] += a0 * b0.z; acc[0][3] += a0 * b0.w;
        acc[0][4] += a0 * b1.x; acc[0][5] += a0 * b1.y; acc[0][6] += a0 * b1.z; acc[0][7] += a0 * b1.w;
        acc[1][0] += a1 * b0.x; acc[1][1] += a1 * b0.y; acc[1][2] += a1 * b0.z; acc[1][3] += a1 * b0.w;
        acc[1][4] += a1 * b1.x; acc[1][5] += a1 * b1.y; acc[1][6] += a1 * b1.z; acc[1][7] += a1 * b1.w;
        acc[2][0] += a2 * b0.x; acc[2][1] += a2 * b0.y; acc[2][2] += a2 * b0.z; acc[2][3] += a2 * b0.w;
        acc[2][4] += a2 * b1.x; acc[2][5] += a2 * b1.y; acc[2][6] += a2 * b1.z; acc[2][7] += a2 * b1.w;
        acc[3][0] += a3 * b0.x; acc[3][1] += a3 * b0.y; acc[3][2] += a3 * b0.z; acc[3][3] += a3 * b0.w;
        acc[3][4] += a3 * b1.x; acc[3][5] += a3 * b1.y; acc[3][6] += a3 * b1.z; acc[3][7] += a3 * b1.w;
    }

    const float qscale = 0.17677669529663687f;   // 32^-0.5
#pragma unroll
    for (int i = 0; i < 4; i++) {
        const int row = m0 + rowb + i;
        const int bb = row >> 12, hh = (row >> 6) & 63, ww = row & 63;
#pragma unroll
        for (int half = 0; half < 2; half++) {
            const int j = n0 + cg * 8 + half * 4;        // global col, mult of 4
            const float4 bv = *(const float4*)(bias + j);
            float4 val;
            val.x = acc[i][half * 4 + 0] + bv.x;
            val.y = acc[i][half * 4 + 1] + bv.y;
            val.z = acc[i][half * 4 + 2] + bv.z;
            val.w = acc[i][half * 4 + 3] + bv.w;
            const int which = j >> 7;
            const int rem = j & 127;
            const int n = rem >> 5, d = rem & 31;
            const int idx = (((bb * 4 + n) * 64 + hh) * 64 + ww) * 32 + d;
            if (which == 0) {
                val.x *= qscale; val.y *= qscale; val.z *= qscale; val.w *= qscale;
                *(float4*)(g_q + idx) = val;
            } else if (which == 1) {
                *(float4*)(g_k + idx) = val;
            } else {
                *(float4*)(g_v + idx) = val;
            }
        }
    }
}

// ---------------- kernel C: 7x7 neighborhood attention, two-phase -------------
// grid(32 h-tiles, 8 bn), block(128) = 2 h-rows x 64 w. Thread-per-query.
// Phase 1: stage K (<=8 rows, 64KB), compute 49 raw scores into regs.
// Phase 2: re-use the same smem for V, softmax + accumulate.
// Layout [row][col][d] with XOR swizzle on d-chunk (chunk ^ (col&7)).
__global__ void __launch_bounds__(128)
natten_kernel(const float* __restrict__ rpb) {
    extern __shared__ float smem[];
    float* skv = smem;                // 8*64*32 = 16384 floats = 64KB
    float* srpb = smem + 16384;       // 169

    const int tid = threadIdx.x;
    const int h0 = blockIdx.x * 2;
    const int bn = blockIdx.y;
    const int b = bn >> 2, n = bn & 3;
    const int base = bn * (64 * 64 * 32);

    const int hs0 = nb_start(h0);
    const int nrows = nb_start(h0 + 1) + 6 - hs0 + 1;   // 7 or 8
    const int nchunks = nrows * 512;                     // rows*64*8 float4s

    // ---- phase 1: stage K ----
    for (int i = tid; i < nchunks; i += 128) {
        const int a = i >> 9;
        const int rem = i & 511;
        const int w = rem >> 3, j = rem & 7;
        ((float4*)skv)[(a * 64 + w) * 8 + (j ^ (w & 7))] =
            *(const float4*)(g_k + base + (hs0 + a) * 2048 + w * 32 + j * 4);
    }
    for (int i = tid; i < 169; i += 128) srpb[i] = rpb[n * 169 + i];
    __syncthreads();

    const int ih = tid >> 6;
    const int w = tid & 63;
    const int h = h0 + ih;
    const int ws = nb_start(w);
    const int hs_q = nb_start(h);
    const int arow0 = hs_q - hs0;
    const int rbase = (hs_q - h + 6) * 13 + (ws - w + 6);

    float4 q4[8];
    {
        const int qoff = base + h * 2048 + w * 32;
#pragma unroll
        for (int j = 0; j < 8; j++) q4[j] = *(const float4*)(g_q + qoff + 4 * j);
    }

    float s[49];
#pragma unroll
    for (int a = 0; a < 7; a++) {
        const int row = arow0 + a;
#pragma unroll
        for (int c = 0; c < 7; c++) {
            const int col = ws + c;
            const float4* kp = ((const float4*)skv) + (row * 64 + col) * 8;
            const int sw = col & 7;
            float p0 = 0.f, p1 = 0.f, p2 = 0.f, p3 = 0.f;
#pragma unroll
            for (int j = 0; j < 8; j++) {
                const float4 kv = kp[j ^ sw];
                p0 += q4[j].x * kv.x;
                p1 += q4[j].y * kv.y;
                p2 += q4[j].z * kv.z;
                p3 += q4[j].w * kv.w;
            }
            s[a * 7 + c] = (p0 + p1) + (p2 + p3) + srpb[rbase + a * 13 + c];
        }
    }

    // softmax weights (raw scores fixed; no online rescale needed)
    float m = s[0];
#pragma unroll
    for (int i = 1; i < 49; i++) m = fmaxf(m, s[i]);
    float l = 0.f;
#pragma unroll
    for (int i = 0; i < 49; i++) { s[i] = __expf(s[i] - m); l += s[i]; }
    const float inv = 1.0f / l;

    __syncthreads();   // everyone done reading K

    // ---- phase 2: stage V into the same buffer ----
    for (int i = tid; i < nchunks; i += 128) {
        const int a = i >> 9;
        const int rem = i & 511;
        const int w_ = rem >> 3, j = rem & 7;
        ((float4*)skv)[(a * 64 + w_) * 8 + (j ^ (w_ & 7))] =
            *(const float4*)(g_v + base + (hs0 + a) * 2048 + w_ * 32 + j * 4);
    }
    __syncthreads();

    float4 acc4[8];
#pragma unroll
    for (int j = 0; j < 8; j++) acc4[j] = make_float4(0.f, 0.f, 0.f, 0.f);

#pragma unroll
    for (int a = 0; a < 7; a++) {
        const int row = arow0 + a;
        const float4* vp = ((const float4*)skv) + (row * 64 + ws) * 8;
#pragma unroll
        for (int j = 0; j < 8; j++) {
            float4 av = acc4[j];
#pragma unroll
            for (int c = 0; c < 7; c++) {
                const int col = ws + c;
                const float4 vv = vp[c * 8 + (j ^ (col & 7))];
                const float p = s[a * 7 + c];
                av.x += p * vv.x;
                av.y += p * vv.y;
                av.z += p * vv.z;
                av.w += p * vv.w;
            }
            acc4[j] = av;
        }
    }

    const int ob = ((b * 64 + h) * 64 + w) * 128 + n * 32;
#pragma unroll
    for (int j = 0; j < 8; j++) {
        float4 o = acc4[j];
        o.x *= inv; o.y *= inv; o.z *= inv; o.w *= inv;
        *(float4*)(g_att + ob + 4 * j) = o;
    }
}

// ---------------- kernel D: proj GEMM [8192,128]x[128,128] + bias -------------
// grid(128,2), block(128).
__global__ void proj_gemm(const float* __restrict__ W,
                          const float* __restrict__ bias,
                          float* __restrict__ out) {
    __shared__ float sa[64 * 132];
    __shared__ float sb[128 * 64];
    const int tid = threadIdx.x;
    const int m0 = blockIdx.x * 64, n0 = blockIdx.y * 64;

#pragma unroll
    for (int r = 0; r < 16; r++) {
        const int id = tid + r * 128;
        const int row = id >> 5, j4 = id & 31;
        *(float4*)(sa + row * 132 + j4 * 4) =
            *(const float4*)(g_att + (m0 + row) * 128 + j4 * 4);
    }
#pragma unroll
    for (int r = 0; r < 16; r++) {
        const int id = tid + r * 128;
        const int kk = id >> 4, j4 = id & 15;
        *(float4*)(sb + kk * 64 + j4 * 4) =
            *(const float4*)(W + kk * 128 + n0 + j4 * 4);
    }
    __syncthreads();

    const int warp = tid >> 5, lane = tid & 31;
    const int rg = lane >> 3, cg = lane & 7;
    const int rowb = warp * 16 + rg * 4;

    float acc[4][8];
#pragma unroll
    for (int i = 0; i < 4; i++)
#pragma unroll
        for (int c = 0; c < 8; c++) acc[i][c] = 0.0f;

#pragma unroll 8
    for (int kk = 0; kk < 128; kk++) {
        const float a0 = sa[(rowb + 0) * 132 + kk];
        const float a1 = sa[(rowb + 1) * 132 + kk];
        const float a2 = sa[(rowb + 2) * 132 + kk];
        const float a3 = sa[(rowb + 3) * 132 + kk];
        const float4 b0 = *(const float4*)(sb + kk * 64 + cg * 8);
        const float4 b1 = *(const float4*)(sb + kk * 64 + cg * 8 + 4);
        acc[0][0] += a0 * b0.x; acc[0][1] += a0 * b0.y; acc[0][2] += a0 * b0.z; acc[0][3] += a0 * b0.w;
        acc[0][4] += a0 * b1.x; acc[0][5] += a0 * b1.y; acc[0][6] += a0 * b1.z; acc[0][7] += a0 * b1.w;
        acc[1][0] += a1 * b0.x; acc[1][1] += a1 * b0.y; acc[1][2] += a1 * b0.z; acc[1][3] += a1 * b0.w;
        acc[1][4] += a1 * b1.x; acc[1][5] += a1 * b1.y; acc[1][6] += a1 * b1.z; acc[1][7] += a1 * b1.w;
        acc[2][0] += a2 * b0.x; acc[2][1] += a2 * b0.y; acc[2][2] += a2 * b0.z; acc[2][3] += a2 * b0.w;
        acc[2][4] += a2 * b1.x; acc[2][5] += a2 * b1.y; acc[2][6] += a2 * b1.z; acc[2][7] += a2 * b1.w;
        acc[3][0] += a3 * b0.x; acc[3][1] += a3 * b0.y; acc[3][2] += a3 * b0.z; acc[3][3] += a3 * b0.w;
        acc[3][4] += a3 * b1.x; acc[3][5] += a3 * b1.y; acc[3][6] += a3 * b1.z; acc[3][7] += a3 * b1.w;
    }

#pragma unroll
    for (int i = 0; i < 4; i++) {
        const int row = m0 + rowb + i;
#pragma unroll
        for (int half = 0; half < 2; half++) {
            const int j = n0 + cg * 8 + half * 4;
            const float4 bv = *(const float4*)(bias + j);
            float4 val;
            val.x = acc[i][half * 4 + 0] + bv.x;
            val.y = acc[i][half * 4 + 1] + bv.y;
            val.z = acc[i][half * 4 + 2] + bv.z;
            val.w = acc[i][half * 4 + 3] + bv.w;
            *(float4*)(out + row * 128 + j) = val;
        }
    }
}

// ---------------- launch ------------------------------------------------------
extern "C" void kernel_launch(void* const* d_in, const int* in_sizes, int n_in,
                              void* d_out, int out_size) {
    const float* x      = (const float*)d_in[0];
    // d_in[1] = cond (unused)
    const int*   t      = (const int*)d_in[2];
    const float* ln_w   = (const float*)d_in[3];
    const float* ln_b   = (const float*)d_in[4];
    const float* qkv_w  = (const float*)d_in[5];
    const float* qkv_b  = (const float*)d_in[6];
    const float* rpb    = (const float*)d_in[7];
    const float* proj_w = (const float*)d_in[8];
    const float* proj_b = (const float*)d_in[9];
    float* out = (float*)d_out;

    const int natten_smem = (16384 + 176) * 4;   // 66,240 B
    cudaFuncSetAttribute(natten_kernel,
                         cudaFuncAttributeMaxDynamicSharedMemorySize, natten_smem);

    adaln_kernel<<<2, 256>>>(t, ln_w, ln_b);
    qkv_gemm<<<dim3(128, 6), 128>>>(x, qkv_w, qkv_b);
    natten_kernel<<<dim3(32, 8), 128, natten_smem>>>(rpb);
    proj_gemm<<<dim3(128, 2), 128>>>(proj_w, proj_b, out);
}

// round 4
// speedup vs baseline: 1.3085x; 1.3085x over previous
#include <cuda_runtime.h>
#include <math.h>
#include <stdint.h>

#define FULL 0xFFFFFFFFu

// ---------------- scratch (device globals; no allocation allowed) -------------
__device__ float g_ada[2 * 256];                 // [B, 2C] scale|shift
__device__ float g_y[2 * 64 * 64 * 128];         // LN output [rows, C]
__device__ float g_q[2 * 4 * 64 * 64 * 32];      // [B,n,H,W,d]
__device__ float g_k[2 * 4 * 64 * 64 * 32];
__device__ float g_v[2 * 4 * 64 * 64 * 32];
__device__ float g_att[2 * 64 * 64 * 128];       // [B,H,W,C]

__device__ __forceinline__ int nb_start(int i) {
    int s = i - 3;
    s = s < 0 ? 0 : s;
    return s > 57 ? 57 : s;   // L-K = 64-7
}

// ---- tf32 helpers ------------------------------------------------------------
__device__ __forceinline__ void tf32_split(float a, uint32_t& hi, uint32_t& lo) {
    uint32_t h;
    asm("cvt.rna.tf32.f32 %0, %1;" : "=r"(h) : "f"(a));
    float r = a - __uint_as_float(h);
    uint32_t l;
    asm("cvt.rna.tf32.f32 %0, %1;" : "=r"(l) : "f"(r));
    hi = h; lo = l;
}

__device__ __forceinline__ void mma_tf32(float* d, const uint32_t* a, const uint32_t* b) {
    asm("mma.sync.aligned.m16n8k8.row.col.f32.tf32.tf32.f32 "
        "{%0,%1,%2,%3}, {%4,%5,%6,%7}, {%8,%9}, {%0,%1,%2,%3};"
        : "+f"(d[0]), "+f"(d[1]), "+f"(d[2]), "+f"(d[3])
        : "r"(a[0]), "r"(a[1]), "r"(a[2]), "r"(a[3]), "r"(b[0]), "r"(b[1]));
}

// ---------------- kernel A: sinusoidal emb + silu + adaLN MLP -----------------
__global__ void adaln_kernel(const int* __restrict__ t,
                             const float* __restrict__ ln_w,
                             const float* __restrict__ ln_b) {
    __shared__ float s_silu[128];
    const int b = blockIdx.x;
    const int tid = threadIdx.x;
    const float tf = (float)t[b] * 40.0f;              // t/100*4000
    if (tid < 64) {
        float f = __expf(-(float)tid * (9.210340371976184f / 63.0f));
        float e = tf * f;
        float se = sinf(e), ce = cosf(e);
        s_silu[tid]      = se / (1.0f + __expf(-se));
        s_silu[tid + 64] = ce / (1.0f + __expf(-ce));
    }
    __syncthreads();
    const int j = tid;                                  // 0..255
    float acc = ln_b[j];
#pragma unroll 16
    for (int k = 0; k < 128; k++) acc += s_silu[k] * ln_w[k * 256 + j];
    g_ada[b * 256 + j] = acc;
}

// ---------------- kernel B: LayerNorm + modulate -> g_y -----------------------
// grid(1024), block(256). warp per row.
__global__ void ln_kernel(const float* __restrict__ x) {
    const int tid = threadIdx.x;
    const int warp = tid >> 5, lane = tid & 31;
    const int row = blockIdx.x * 8 + warp;
    const int b = row >> 12;

    const float4 xv = *(const float4*)(x + row * 128 + lane * 4);
    float sum = xv.x + xv.y + xv.z + xv.w;
    float sq  = xv.x * xv.x + xv.y * xv.y + xv.z * xv.z + xv.w * xv.w;
#pragma unroll
    for (int o = 16; o; o >>= 1) {
        sum += __shfl_xor_sync(FULL, sum, o);
        sq  += __shfl_xor_sync(FULL, sq, o);
    }
    const float mean = sum * (1.0f / 128.0f);
    const float var  = sq * (1.0f / 128.0f) - mean * mean;
    const float rstd = rsqrtf(var + 1e-5f);

    const float4 sc = *(const float4*)(g_ada + b * 256 + lane * 4);
    const float4 sh = *(const float4*)(g_ada + b * 256 + 128 + lane * 4);
    float4 yv;
    yv.x = (xv.x - mean) * rstd * (1.0f + sc.x) + sh.x;
    yv.y = (xv.y - mean) * rstd * (1.0f + sc.y) + sh.y;
    yv.z = (xv.z - mean) * rstd * (1.0f + sc.z) + sh.z;
    yv.w = (xv.w - mean) * rstd * (1.0f + sc.w) + sh.w;
    *(float4*)(g_y + row * 128 + lane * 4) = yv;
}

// ---------------- kernel C: qkv GEMM (tensor core, 3xTF32) --------------------
// grid(128, 6), block(128) = 4 warps (2x2). tile 64x64, warp tile 32x32.
// A = g_y (fp32), B = qkv_w. D scattered to g_q/g_k/g_v.
__global__ void __launch_bounds__(128)
qkv_gemm_tc(const float* __restrict__ W, const float* __restrict__ bias) {
    extern __shared__ float smem[];
    float* sa = smem;              // [64][132]
    float* sb = smem + 64 * 132;   // [128][72]

    const int tid = threadIdx.x;
    const int m0 = blockIdx.x * 64, n0 = blockIdx.y * 64;

    // stage A
#pragma unroll
    for (int r = 0; r < 16; r++) {
        const int id = tid + r * 128;
        const int row = id >> 5, j4 = id & 31;
        *(float4*)(sa + row * 132 + j4 * 4) =
            *(const float4*)(g_y + (m0 + row) * 128 + j4 * 4);
    }
    // stage B: W[k][n0+j], stride 384
#pragma unroll
    for (int r = 0; r < 16; r++) {
        const int id = tid + r * 128;
        const int kk = id >> 4, j4 = id & 15;
        *(float4*)(sb + kk * 72 + j4 * 4) =
            *(const float4*)(W + kk * 384 + n0 + j4 * 4);
    }
    __syncthreads();

    const int lane = tid & 31, warp = tid >> 5;
    const int wm = warp & 1, wn = warp >> 1;
    const int g = lane >> 2, tig = lane & 3;

    float d[2][4][4];
#pragma unroll
    for (int fm = 0; fm < 2; fm++)
#pragma unroll
        for (int fn = 0; fn < 4; fn++)
#pragma unroll
            for (int e = 0; e < 4; e++) d[fm][fn][e] = 0.0f;

#pragma unroll 4
    for (int k0 = 0; k0 < 128; k0 += 8) {
        uint32_t ahi[2][4], alo[2][4];
#pragma unroll
        for (int fm = 0; fm < 2; fm++) {
            const int r = wm * 32 + fm * 16 + g;
            tf32_split(sa[(r    ) * 132 + k0 + tig    ], ahi[fm][0], alo[fm][0]);
            tf32_split(sa[(r + 8) * 132 + k0 + tig    ], ahi[fm][1], alo[fm][1]);
            tf32_split(sa[(r    ) * 132 + k0 + tig + 4], ahi[fm][2], alo[fm][2]);
            tf32_split(sa[(r + 8) * 132 + k0 + tig + 4], ahi[fm][3], alo[fm][3]);
        }
        uint32_t bhi[4][2], blo[4][2];
#pragma unroll
        for (int fn = 0; fn < 4; fn++) {
            const int c = wn * 32 + fn * 8 + g;
            tf32_split(sb[(k0 + tig    ) * 72 + c], bhi[fn][0], blo[fn][0]);
            tf32_split(sb[(k0 + tig + 4) * 72 + c], bhi[fn][1], blo[fn][1]);
        }
#pragma unroll
        for (int fm = 0; fm < 2; fm++)
#pragma unroll
            for (int fn = 0; fn < 4; fn++) {
                mma_tf32(d[fm][fn], ahi[fm], bhi[fn]);
                mma_tf32(d[fm][fn], ahi[fm], blo[fn]);
                mma_tf32(d[fm][fn], alo[fm], bhi[fn]);
            }
    }

    // epilogue: scatter
    const float qscale = 0.17677669529663687f;   // 32^-0.5
#pragma unroll
    for (int fn = 0; fn < 4; fn++) {
        const int j0 = n0 + wn * 32 + fn * 8 + 2 * tig;
        const float bv0 = bias[j0], bv1 = bias[j0 + 1];
        const int which = j0 >> 7;
        const int rem = j0 & 127;
        const int nh = rem >> 5, dd = rem & 31;
#pragma unroll
        for (int fm = 0; fm < 2; fm++) {
#pragma unroll
            for (int half = 0; half < 2; half++) {
                const int row = m0 + wm * 32 + fm * 16 + g + half * 8;
                const int bb = row >> 12, hh = (row >> 6) & 63, ww = row & 63;
                const int idx = (((bb * 4 + nh) * 64 + hh) * 64 + ww) * 32 + dd;
                float v0 = d[fm][fn][half * 2 + 0] + bv0;
                float v1 = d[fm][fn][half * 2 + 1] + bv1;
                if (which == 0) {
                    v0 *= qscale; v1 *= qscale;
                    *(float2*)(g_q + idx) = make_float2(v0, v1);
                } else if (which == 1) {
                    *(float2*)(g_k + idx) = make_float2(v0, v1);
                } else {
                    *(float2*)(g_v + idx) = make_float2(v0, v1);
                }
            }
        }
    }
}

// ---------------- kernel D: 7x7 neighborhood attention, two-phase -------------
// grid(32 h-tiles, 8 bn), block(128) = 2 h-rows x 64 w. Thread-per-query.
__global__ void __launch_bounds__(128)
natten_kernel(const float* __restrict__ rpb) {
    extern __shared__ float smem[];
    float* skv = smem;                // 8*64*32 = 16384 floats = 64KB
    float* srpb = smem + 16384;       // 169

    const int tid = threadIdx.x;
    const int h0 = blockIdx.x * 2;
    const int bn = blockIdx.y;
    const int b = bn >> 2, n = bn & 3;
    const int base = bn * (64 * 64 * 32);

    const int hs0 = nb_start(h0);
    const int nrows = nb_start(h0 + 1) + 6 - hs0 + 1;   // 7 or 8
    const int nchunks = nrows * 512;                     // rows*64*8 float4s

    // ---- phase 1: stage K ----
    for (int i = tid; i < nchunks; i += 128) {
        const int a = i >> 9;
        const int rem = i & 511;
        const int w = rem >> 3, j = rem & 7;
        ((float4*)skv)[(a * 64 + w) * 8 + (j ^ (w & 7))] =
            *(const float4*)(g_k + base + (hs0 + a) * 2048 + w * 32 + j * 4);
    }
    for (int i = tid; i < 169; i += 128) srpb[i] = rpb[n * 169 + i];
    __syncthreads();

    const int ih = tid >> 6;
    const int w = tid & 63;
    const int h = h0 + ih;
    const int ws = nb_start(w);
    const int hs_q = nb_start(h);
    const int arow0 = hs_q - hs0;
    const int rbase = (hs_q - h + 6) * 13 + (ws - w + 6);

    float4 q4[8];
    {
        const int qoff = base + h * 2048 + w * 32;
#pragma unroll
        for (int j = 0; j < 8; j++) q4[j] = *(const float4*)(g_q + qoff + 4 * j);
    }

    float s[49];
#pragma unroll
    for (int a = 0; a < 7; a++) {
        const int row = arow0 + a;
#pragma unroll
        for (int c = 0; c < 7; c++) {
            const int col = ws + c;
            const float4* kp = ((const float4*)skv) + (row * 64 + col) * 8;
            const int sw = col & 7;
            float p0 = 0.f, p1 = 0.f, p2 = 0.f, p3 = 0.f;
#pragma unroll
            for (int j = 0; j < 8; j++) {
                const float4 kv = kp[j ^ sw];
                p0 += q4[j].x * kv.x;
                p1 += q4[j].y * kv.y;
                p2 += q4[j].z * kv.z;
                p3 += q4[j].w * kv.w;
            }
            s[a * 7 + c] = (p0 + p1) + (p2 + p3) + srpb[rbase + a * 13 + c];
        }
    }

    float m = s[0];
#pragma unroll
    for (int i = 1; i < 49; i++) m = fmaxf(m, s[i]);
    float l = 0.f;
#pragma unroll
    for (int i = 0; i < 49; i++) { s[i] = __expf(s[i] - m); l += s[i]; }
    const float inv = 1.0f / l;

    __syncthreads();   // everyone done reading K

    // ---- phase 2: stage V into the same buffer ----
    for (int i = tid; i < nchunks; i += 128) {
        const int a = i >> 9;
        const int rem = i & 511;
        const int w_ = rem >> 3, j = rem & 7;
        ((float4*)skv)[(a * 64 + w_) * 8 + (j ^ (w_ & 7))] =
            *(const float4*)(g_v + base + (hs0 + a) * 2048 + w_ * 32 + j * 4);
    }
    __syncthreads();

    float4 acc4[8];
#pragma unroll
    for (int j = 0; j < 8; j++) acc4[j] = make_float4(0.f, 0.f, 0.f, 0.f);

#pragma unroll
    for (int a = 0; a < 7; a++) {
        const int row = arow0 + a;
        const float4* vp = ((const float4*)skv) + (row * 64 + ws) * 8;
#pragma unroll
        for (int j = 0; j < 8; j++) {
            float4 av = acc4[j];
#pragma unroll
            for (int c = 0; c < 7; c++) {
                const int col = ws + c;
                const float4 vv = vp[c * 8 + (j ^ (col & 7))];
                const float p = s[a * 7 + c];
                av.x += p * vv.x;
                av.y += p * vv.y;
                av.z += p * vv.z;
                av.w += p * vv.w;
            }
            acc4[j] = av;
        }
    }

    const int ob = ((b * 64 + h) * 64 + w) * 128 + n * 32;
#pragma unroll
    for (int j = 0; j < 8; j++) {
        float4 o = acc4[j];
        o.x *= inv; o.y *= inv; o.z *= inv; o.w *= inv;
        *(float4*)(g_att + ob + 4 * j) = o;
    }
}

// ---------------- kernel E: proj GEMM (tensor core, 3xTF32) -------------------
// grid(128, 2), block(128). A = g_att, B = proj_w, out + bias.
__global__ void __launch_bounds__(128)
proj_gemm_tc(const float* __restrict__ W, const float* __restrict__ bias,
             float* __restrict__ out) {
    extern __shared__ float smem[];
    float* sa = smem;              // [64][132]
    float* sb = smem + 64 * 132;   // [128][72]

    const int tid = threadIdx.x;
    const int m0 = blockIdx.x * 64, n0 = blockIdx.y * 64;

#pragma unroll
    for (int r = 0; r < 16; r++) {
        const int id = tid + r * 128;
        const int row = id >> 5, j4 = id & 31;
        *(float4*)(sa + row * 132 + j4 * 4) =
            *(const float4*)(g_att + (m0 + row) * 128 + j4 * 4);
    }
#pragma unroll
    for (int r = 0; r < 16; r++) {
        const int id = tid + r * 128;
        const int kk = id >> 4, j4 = id & 15;
        *(float4*)(sb + kk * 72 + j4 * 4) =
            *(const float4*)(W + kk * 128 + n0 + j4 * 4);
    }
    __syncthreads();

    const int lane = tid & 31, warp = tid >> 5;
    const int wm = warp & 1, wn = warp >> 1;
    const int g = lane >> 2, tig = lane & 3;

    float d[2][4][4];
#pragma unroll
    for (int fm = 0; fm < 2; fm++)
#pragma unroll
        for (int fn = 0; fn < 4; fn++)
#pragma unroll
            for (int e = 0; e < 4; e++) d[fm][fn][e] = 0.0f;

#pragma unroll 4
    for (int k0 = 0; k0 < 128; k0 += 8) {
        uint32_t ahi[2][4], alo[2][4];
#pragma unroll
        for (int fm = 0; fm < 2; fm++) {
            const int r = wm * 32 + fm * 16 + g;
            tf32_split(sa[(r    ) * 132 + k0 + tig    ], ahi[fm][0], alo[fm][0]);
            tf32_split(sa[(r + 8) * 132 + k0 + tig    ], ahi[fm][1], alo[fm][1]);
            tf32_split(sa[(r    ) * 132 + k0 + tig + 4], ahi[fm][2], alo[fm][2]);
            tf32_split(sa[(r + 8) * 132 + k0 + tig + 4], ahi[fm][3], alo[fm][3]);
        }
        uint32_t bhi[4][2], blo[4][2];
#pragma unroll
        for (int fn = 0; fn < 4; fn++) {
            const int c = wn * 32 + fn * 8 + g;
            tf32_split(sb[(k0 + tig    ) * 72 + c], bhi[fn][0], blo[fn][0]);
            tf32_split(sb[(k0 + tig + 4) * 72 + c], bhi[fn][1], blo[fn][1]);
        }
#pragma unroll
        for (int fm = 0; fm < 2; fm++)
#pragma unroll
            for (int fn = 0; fn < 4; fn++) {
                mma_tf32(d[fm][fn], ahi[fm], bhi[fn]);
                mma_tf32(d[fm][fn], ahi[fm], blo[fn]);
                mma_tf32(d[fm][fn], alo[fm], bhi[fn]);
            }
    }

#pragma unroll
    for (int fn = 0; fn < 4; fn++) {
        const int j0 = n0 + wn * 32 + fn * 8 + 2 * tig;
        const float bv0 = bias[j0], bv1 = bias[j0 + 1];
#pragma unroll
        for (int fm = 0; fm < 2; fm++) {
#pragma unroll
            for (int half = 0; half < 2; half++) {
                const int row = m0 + wm * 32 + fm * 16 + g + half * 8;
                float v0 = d[fm][fn][half * 2 + 0] + bv0;
                float v1 = d[fm][fn][half * 2 + 1] + bv1;
                *(float2*)(out + row * 128 + j0) = make_float2(v0, v1);
            }
        }
    }
}

// ---------------- launch ------------------------------------------------------
extern "C" void kernel_launch(void* const* d_in, const int* in_sizes, int n_in,
                              void* d_out, int out_size) {
    const float* x      = (const float*)d_in[0];
    // d_in[1] = cond (unused)
    const int*   t      = (const int*)d_in[2];
    const float* ln_w   = (const float*)d_in[3];
    const float* ln_b   = (const float*)d_in[4];
    const float* qkv_w  = (const float*)d_in[5];
    const float* qkv_b  = (const float*)d_in[6];
    const float* rpb    = (const float*)d_in[7];
    const float* proj_w = (const float*)d_in[8];
    const float* proj_b = (const float*)d_in[9];
    float* out = (float*)d_out;

    const int gemm_smem = (64 * 132 + 128 * 72) * 4;   // 70,656 B
    const int natten_smem = (16384 + 176) * 4;         // 66,240 B
    cudaFuncSetAttribute(qkv_gemm_tc,
                         cudaFuncAttributeMaxDynamicSharedMemorySize, gemm_smem);
    cudaFuncSetAttribute(proj_gemm_tc,
                         cudaFuncAttributeMaxDynamicSharedMemorySize, gemm_smem);
    cudaFuncSetAttribute(natten_kernel,
                         cudaFuncAttributeMaxDynamicSharedMemorySize, natten_smem);

    adaln_kernel<<<2, 256>>>(t, ln_w, ln_b);
    ln_kernel<<<1024, 256>>>(x);
    qkv_gemm_tc<<<dim3(128, 6), 128, gemm_smem>>>(qkv_w, qkv_b);
    natten_kernel<<<dim3(32, 8), 128, natten_smem>>>(rpb);
    proj_gemm_tc<<<dim3(128, 2), 128, gemm_smem>>>(proj_w, proj_b, out);
}

// round 5
// speedup vs baseline: 1.3547x; 1.0353x over previous
#include <cuda_runtime.h>
#include <cuda_bf16.h>
#include <math.h>
#include <stdint.h>

#define FULL 0xFFFFFFFFu

// ---------------- scratch (device globals; no allocation allowed) -------------
__device__ float g_ada[2 * 256];                 // [B, 2C] scale|shift
__device__ float g_y[2 * 64 * 64 * 128];         // LN output [rows, C]
__device__ float g_q[2 * 4 * 64 * 64 * 32];      // [B,n,H,W,d]
__device__ float g_k[2 * 4 * 64 * 64 * 32];
__device__ float g_v[2 * 4 * 64 * 64 * 32];
__device__ float g_att[2 * 64 * 64 * 128];       // [B,H,W,C]

__device__ __forceinline__ int nb_start(int i) {
    int s = i - 3;
    s = s < 0 ? 0 : s;
    return s > 57 ? 57 : s;   // L-K = 64-7
}

// ---- bf16 2-term split helpers ----------------------------------------------
// pack: low16 = bf16(x) (the "hi" term, k-slot 2k), high16 = bf16(x - hi) (slot 2k+1)
__device__ __forceinline__ uint32_t bf16_split_pack(float x) {
    __nv_bfloat16 h = __float2bfloat16(x);
    float r = x - __bfloat162float(h);
    __nv_bfloat16 l = __float2bfloat16(r);
    return (uint32_t)__bfloat16_as_ushort(h) |
           ((uint32_t)__bfloat16_as_ushort(l) << 16);
}

__device__ __forceinline__ void mma_bf16(float* d, const uint32_t* a, const uint32_t* b) {
    asm("mma.sync.aligned.m16n8k16.row.col.f32.bf16.bf16.f32 "
        "{%0,%1,%2,%3}, {%4,%5,%6,%7}, {%8,%9}, {%0,%1,%2,%3};"
        : "+f"(d[0]), "+f"(d[1]), "+f"(d[2]), "+f"(d[3])
        : "r"(a[0]), "r"(a[1]), "r"(a[2]), "r"(a[3]), "r"(b[0]), "r"(b[1]));
}

// ---------------- kernel A: sinusoidal emb + silu + adaLN MLP -----------------
__global__ void adaln_kernel(const int* __restrict__ t,
                             const float* __restrict__ ln_w,
                             const float* __restrict__ ln_b) {
    __shared__ float s_silu[128];
    const int b = blockIdx.x;
    const int tid = threadIdx.x;
    const float tf = (float)t[b] * 40.0f;              // t/100*4000
    if (tid < 64) {
        float f = __expf(-(float)tid * (9.210340371976184f / 63.0f));
        float e = tf * f;
        float se = sinf(e), ce = cosf(e);
        s_silu[tid]      = se / (1.0f + __expf(-se));
        s_silu[tid + 64] = ce / (1.0f + __expf(-ce));
    }
    __syncthreads();
    const int j = tid;                                  // 0..255
    float acc = ln_b[j];
#pragma unroll 16
    for (int k = 0; k < 128; k++) acc += s_silu[k] * ln_w[k * 256 + j];
    g_ada[b * 256 + j] = acc;
}

// ---------------- kernel B: LayerNorm + modulate -> g_y -----------------------
__global__ void ln_kernel(const float* __restrict__ x) {
    const int tid = threadIdx.x;
    const int warp = tid >> 5, lane = tid & 31;
    const int row = blockIdx.x * 8 + warp;
    const int b = row >> 12;

    const float4 xv = *(const float4*)(x + row * 128 + lane * 4);
    float sum = xv.x + xv.y + xv.z + xv.w;
    float sq  = xv.x * xv.x + xv.y * xv.y + xv.z * xv.z + xv.w * xv.w;
#pragma unroll
    for (int o = 16; o; o >>= 1) {
        sum += __shfl_xor_sync(FULL, sum, o);
        sq  += __shfl_xor_sync(FULL, sq, o);
    }
    const float mean = sum * (1.0f / 128.0f);
    const float var  = sq * (1.0f / 128.0f) - mean * mean;
    const float rstd = rsqrtf(var + 1e-5f);

    const float4 sc = *(const float4*)(g_ada + b * 256 + lane * 4);
    const float4 sh = *(const float4*)(g_ada + b * 256 + 128 + lane * 4);
    float4 yv;
    yv.x = (xv.x - mean) * rstd * (1.0f + sc.x) + sh.x;
    yv.y = (xv.y - mean) * rstd * (1.0f + sc.y) + sh.y;
    yv.z = (xv.z - mean) * rstd * (1.0f + sc.z) + sh.z;
    yv.w = (xv.w - mean) * rstd * (1.0f + sc.w) + sh.w;
    *(float4*)(g_y + row * 128 + lane * 4) = yv;
}

// ---------------- kernel C: qkv GEMM (bf16x3 split tensor core) ---------------
// grid(128, 6), block(128) = 4 warps (2x2). tile 64x64, warp tile 32x32.
__global__ void __launch_bounds__(128)
qkv_gemm_tc(const float* __restrict__ W, const float* __restrict__ bias) {
    extern __shared__ uint32_t smem[];
    uint32_t* sa = smem;              // [64][132] packed bf16x2(hi,lo)
    uint32_t* sb = smem + 64 * 132;   // [128][72]

    const int tid = threadIdx.x;
    const int m0 = blockIdx.x * 64, n0 = blockIdx.y * 64;

    // stage A (split once)
#pragma unroll
    for (int r = 0; r < 16; r++) {
        const int id = tid + r * 128;
        const int row = id >> 5, j4 = id & 31;
        const float4 v = *(const float4*)(g_y + (m0 + row) * 128 + j4 * 4);
        uint32_t* p = sa + row * 132 + j4 * 4;
        p[0] = bf16_split_pack(v.x); p[1] = bf16_split_pack(v.y);
        p[2] = bf16_split_pack(v.z); p[3] = bf16_split_pack(v.w);
    }
    // stage B: W[k][n0+j], stride 384
#pragma unroll
    for (int r = 0; r < 16; r++) {
        const int id = tid + r * 128;
        const int kk = id >> 4, j4 = id & 15;
        const float4 v = *(const float4*)(W + kk * 384 + n0 + j4 * 4);
        uint32_t* p = sb + kk * 72 + j4 * 4;
        p[0] = bf16_split_pack(v.x); p[1] = bf16_split_pack(v.y);
        p[2] = bf16_split_pack(v.z); p[3] = bf16_split_pack(v.w);
    }
    __syncthreads();

    const int lane = tid & 31, warp = tid >> 5;
    const int wm = warp & 1, wn = warp >> 1;
    const int g = lane >> 2, tig = lane & 3;

    float d[2][4][4];
#pragma unroll
    for (int fm = 0; fm < 2; fm++)
#pragma unroll
        for (int fn = 0; fn < 4; fn++)
#pragma unroll
            for (int e = 0; e < 4; e++) d[fm][fn][e] = 0.0f;

#pragma unroll 4
    for (int k0 = 0; k0 < 128; k0 += 8) {
        uint32_t a[2][4];
#pragma unroll
        for (int fm = 0; fm < 2; fm++) {
            const int r = wm * 32 + fm * 16 + g;
            a[fm][0] = sa[(r    ) * 132 + k0 + tig];
            a[fm][1] = sa[(r + 8) * 132 + k0 + tig];
            a[fm][2] = sa[(r    ) * 132 + k0 + tig + 4];
            a[fm][3] = sa[(r + 8) * 132 + k0 + tig + 4];
        }
#pragma unroll
        for (int fn = 0; fn < 4; fn++) {
            const int c = wn * 32 + fn * 8 + g;
            const uint32_t p0 = sb[(k0 + tig    ) * 72 + c];
            const uint32_t p1 = sb[(k0 + tig + 4) * 72 + c];
            uint32_t bhh[2] = { __byte_perm(p0, p0, 0x1010),
                                __byte_perm(p1, p1, 0x1010) };
            uint32_t bl0[2] = { __byte_perm(p0, 0, 0x4432),
                                __byte_perm(p1, 0, 0x4432) };
#pragma unroll
            for (int fm = 0; fm < 2; fm++) {
                mma_bf16(d[fm][fn], a[fm], bhh);
                mma_bf16(d[fm][fn], a[fm], bl0);
            }
        }
    }

    // epilogue: scatter
    const float qscale = 0.17677669529663687f;   // 32^-0.5
#pragma unroll
    for (int fn = 0; fn < 4; fn++) {
        const int j0 = n0 + wn * 32 + fn * 8 + 2 * tig;
        const float bv0 = bias[j0], bv1 = bias[j0 + 1];
        const int which = j0 >> 7;
        const int rem = j0 & 127;
        const int nh = rem >> 5, dd = rem & 31;
#pragma unroll
        for (int fm = 0; fm < 2; fm++) {
#pragma unroll
            for (int half = 0; half < 2; half++) {
                const int row = m0 + wm * 32 + fm * 16 + g + half * 8;
                const int bb = row >> 12, hh = (row >> 6) & 63, ww = row & 63;
                const int idx = (((bb * 4 + nh) * 64 + hh) * 64 + ww) * 32 + dd;
                float v0 = d[fm][fn][half * 2 + 0] + bv0;
                float v1 = d[fm][fn][half * 2 + 1] + bv1;
                if (which == 0) {
                    v0 *= qscale; v1 *= qscale;
                    *(float2*)(g_q + idx) = make_float2(v0, v1);
                } else if (which == 1) {
                    *(float2*)(g_k + idx) = make_float2(v0, v1);
                } else {
                    *(float2*)(g_v + idx) = make_float2(v0, v1);
                }
            }
        }
    }
}

// ---------------- kernel D: 7x7 neighborhood attention ------------------------
// grid(64 h, 8 bn), block(128) = 64 queries x 2 d-halves. Two-phase K->V smem.
__global__ void __launch_bounds__(128, 3)
natten_kernel(const float* __restrict__ rpb) {
    extern __shared__ float smem_f[];
    float* skv = smem_f;              // 7*64*32 = 14336 floats = 57344B
    float* srpb = smem_f + 14336;     // 169

    const int tid = threadIdx.x;
    const int h  = blockIdx.x;
    const int bn = blockIdx.y;
    const int b = bn >> 2, n = bn & 3;
    const int base = bn * (64 * 64 * 32);

    const int hs = nb_start(h);

    // ---- phase 1: stage K rows hs..hs+6 ----
#pragma unroll 4
    for (int it = 0; it < 28; it++) {
        const int i = tid + it * 128;          // 28*128 = 3584 float4s
        const int a = i >> 9;
        const int rem = i & 511;
        const int w = rem >> 3, j = rem & 7;
        ((float4*)skv)[(a * 64 + w) * 8 + (j ^ (w & 7))] =
            *(const float4*)(g_k + base + (hs + a) * 2048 + w * 32 + j * 4);
    }
    for (int i = tid; i < 169; i += 128) srpb[i] = rpb[n * 169 + i];

    const int qw = tid >> 1;           // query column 0..63
    const int half = tid & 1;          // d-half: dims half*16..half*16+15
    const int ws = nb_start(qw);
    const int rbase = (hs - h + 6) * 13 + (ws - qw + 6);

    float4 q4[4];
    {
        const int qoff = base + h * 2048 + qw * 32 + half * 16;
#pragma unroll
        for (int j = 0; j < 4; j++) q4[j] = *(const float4*)(g_q + qoff + 4 * j);
    }
    __syncthreads();

    float s[49];
#pragma unroll
    for (int a = 0; a < 7; a++) {
#pragma unroll
        for (int c = 0; c < 7; c++) {
            const int col = ws + c;
            const float4* kp = ((const float4*)skv) + (a * 64 + col) * 8;
            const int sw = col & 7;
            float p0 = 0.f, p1 = 0.f, p2 = 0.f, p3 = 0.f;
#pragma unroll
            for (int j = 0; j < 4; j++) {
                const float4 kv = kp[(half * 4 + j) ^ sw];
                p0 += q4[j].x * kv.x;
                p1 += q4[j].y * kv.y;
                p2 += q4[j].z * kv.z;
                p3 += q4[j].w * kv.w;
            }
            float part = (p0 + p1) + (p2 + p3);
            part += __shfl_xor_sync(FULL, part, 1);   // combine d-halves
            s[a * 7 + c] = part + srpb[rbase + a * 13 + c];
        }
    }

    float m = s[0];
#pragma unroll
    for (int i = 1; i < 49; i++) m = fmaxf(m, s[i]);
    float l = 0.f;
#pragma unroll
    for (int i = 0; i < 49; i++) { s[i] = __expf(s[i] - m); l += s[i]; }
    const float inv = 1.0f / l;

    __syncthreads();   // everyone done reading K

    // ---- phase 2: stage V into the same buffer ----
#pragma unroll 4
    for (int it = 0; it < 28; it++) {
        const int i = tid + it * 128;
        const int a = i >> 9;
        const int rem = i & 511;
        const int w_ = rem >> 3, j = rem & 7;
        ((float4*)skv)[(a * 64 + w_) * 8 + (j ^ (w_ & 7))] =
            *(const float4*)(g_v + base + (hs + a) * 2048 + w_ * 32 + j * 4);
    }
    __syncthreads();

    float4 acc4[4];
#pragma unroll
    for (int j = 0; j < 4; j++) acc4[j] = make_float4(0.f, 0.f, 0.f, 0.f);

#pragma unroll
    for (int a = 0; a < 7; a++) {
        const float4* vp = ((const float4*)skv) + (a * 64 + ws) * 8;
#pragma unroll
        for (int c = 0; c < 7; c++) {
            const int col = ws + c;
            const int sw = col & 7;
            const float p = s[a * 7 + c];
#pragma unroll
            for (int j = 0; j < 4; j++) {
                const float4 vv = vp[c * 8 + ((half * 4 + j) ^ sw)];
                acc4[j].x += p * vv.x;
                acc4[j].y += p * vv.y;
                acc4[j].z += p * vv.z;
                acc4[j].w += p * vv.w;
            }
        }
    }

    const int ob = ((b * 64 + h) * 64 + qw) * 128 + n * 32 + half * 16;
#pragma unroll
    for (int j = 0; j < 4; j++) {
        float4 o = acc4[j];
        o.x *= inv; o.y *= inv; o.z *= inv; o.w *= inv;
        *(float4*)(g_att + ob + 4 * j) = o;
    }
}

// ---------------- kernel E: proj GEMM (bf16x3 split tensor core) --------------
__global__ void __launch_bounds__(128)
proj_gemm_tc(const float* __restrict__ W, const float* __restrict__ bias,
             float* __restrict__ out) {
    extern __shared__ uint32_t smem[];
    uint32_t* sa = smem;              // [64][132]
    uint32_t* sb = smem + 64 * 132;   // [128][72]

    const int tid = threadIdx.x;
    const int m0 = blockIdx.x * 64, n0 = blockIdx.y * 64;

#pragma unroll
    for (int r = 0; r < 16; r++) {
        const int id = tid + r * 128;
        const int row = id >> 5, j4 = id & 31;
        const float4 v = *(const float4*)(g_att + (m0 + row) * 128 + j4 * 4);
        uint32_t* p = sa + row * 132 + j4 * 4;
        p[0] = bf16_split_pack(v.x); p[1] = bf16_split_pack(v.y);
        p[2] = bf16_split_pack(v.z); p[3] = bf16_split_pack(v.w);
    }
#pragma unroll
    for (int r = 0; r < 16; r++) {
        const int id = tid + r * 128;
        const int kk = id >> 4, j4 = id & 15;
        const float4 v = *(const float4*)(W + kk * 128 + n0 + j4 * 4);
        uint32_t* p = sb + kk * 72 + j4 * 4;
        p[0] = bf16_split_pack(v.x); p[1] = bf16_split_pack(v.y);
        p[2] = bf16_split_pack(v.z); p[3] = bf16_split_pack(v.w);
    }
    __syncthreads();

    const int lane = tid & 31, warp = tid >> 5;
    const int wm = warp & 1, wn = warp >> 1;
    const int g = lane >> 2, tig = lane & 3;

    float d[2][4][4];
#pragma unroll
    for (int fm = 0; fm < 2; fm++)
#pragma unroll
        for (int fn = 0; fn < 4; fn++)
#pragma unroll
            for (int e = 0; e < 4; e++) d[fm][fn][e] = 0.0f;

#pragma unroll 4
    for (int k0 = 0; k0 < 128; k0 += 8) {
        uint32_t a[2][4];
#pragma unroll
        for (int fm = 0; fm < 2; fm++) {
            const int r = wm * 32 + fm * 16 + g;
            a[fm][0] = sa[(r    ) * 132 + k0 + tig];
            a[fm][1] = sa[(r + 8) * 132 + k0 + tig];
            a[fm][2] = sa[(r    ) * 132 + k0 + tig + 4];
            a[fm][3] = sa[(r + 8) * 132 + k0 + tig + 4];
        }
#pragma unroll
        for (int fn = 0; fn < 4; fn++) {
            const int c = wn * 32 + fn * 8 + g;
            const uint32_t p0 = sb[(k0 + tig    ) * 72 + c];
            const uint32_t p1 = sb[(k0 + tig + 4) * 72 + c];
            uint32_t bhh[2] = { __byte_perm(p0, p0, 0x1010),
                                __byte_perm(p1, p1, 0x1010) };
            uint32_t bl0[2] = { __byte_perm(p0, 0, 0x4432),
                                __byte_perm(p1, 0, 0x4432) };
#pragma unroll
            for (int fm = 0; fm < 2; fm++) {
                mma_bf16(d[fm][fn], a[fm], bhh);
                mma_bf16(d[fm][fn], a[fm], bl0);
            }
        }
    }

#pragma unroll
    for (int fn = 0; fn < 4; fn++) {
        const int j0 = n0 + wn * 32 + fn * 8 + 2 * tig;
        const float bv0 = bias[j0], bv1 = bias[j0 + 1];
#pragma unroll
        for (int fm = 0; fm < 2; fm++) {
#pragma unroll
            for (int half = 0; half < 2; half++) {
                const int row = m0 + wm * 32 + fm * 16 + g + half * 8;
                float v0 = d[fm][fn][half * 2 + 0] + bv0;
                float v1 = d[fm][fn][half * 2 + 1] + bv1;
                *(float2*)(out + row * 128 + j0) = make_float2(v0, v1);
            }
        }
    }
}

// ---------------- launch ------------------------------------------------------
extern "C" void kernel_launch(void* const* d_in, const int* in_sizes, int n_in,
                              void* d_out, int out_size) {
    const float* x      = (const float*)d_in[0];
    // d_in[1] = cond (unused)
    const int*   t      = (const int*)d_in[2];
    const float* ln_w   = (const float*)d_in[3];
    const float* ln_b   = (const float*)d_in[4];
    const float* qkv_w  = (const float*)d_in[5];
    const float* qkv_b  = (const float*)d_in[6];
    const float* rpb    = (const float*)d_in[7];
    const float* proj_w = (const float*)d_in[8];
    const float* proj_b = (const float*)d_in[9];
    float* out = (float*)d_out;

    const int gemm_smem = (64 * 132 + 128 * 72) * 4;   // 70,656 B
    const int natten_smem = (14336 + 176) * 4;         // 58,048 B
    cudaFuncSetAttribute(qkv_gemm_tc,
                         cudaFuncAttributeMaxDynamicSharedMemorySize, gemm_smem);
    cudaFuncSetAttribute(proj_gemm_tc,
                         cudaFuncAttributeMaxDynamicSharedMemorySize, gemm_smem);
    cudaFuncSetAttribute(natten_kernel,
                         cudaFuncAttributeMaxDynamicSharedMemorySize, natten_smem);

    adaln_kernel<<<2, 256>>>(t, ln_w, ln_b);
    ln_kernel<<<1024, 256>>>(x);
    qkv_gemm_tc<<<dim3(128, 6), 128, gemm_smem>>>(qkv_w, qkv_b);
    natten_kernel<<<dim3(64, 8), 128, natten_smem>>>(rpb);
    proj_gemm_tc<<<dim3(128, 2), 128, gemm_smem>>>(proj_w, proj_b, out);
}

// round 6
// speedup vs baseline: 1.4527x; 1.0723x over previous
#include <cuda_runtime.h>
#include <cuda_bf16.h>
#include <math.h>
#include <stdint.h>

#define FULL 0xFFFFFFFFu

// ---------------- scratch (device globals; no allocation allowed) -------------
__device__ float g_ada[2 * 256];                 // [B, 2C] scale|shift
__device__ float g_y[2 * 64 * 64 * 128];         // LN output [rows, C]
__device__ float g_q[2 * 4 * 64 * 64 * 32];      // [B,n,H,W,d]
__device__ float g_k[2 * 4 * 64 * 64 * 32];
__device__ float g_v[2 * 4 * 64 * 64 * 32];
__device__ float g_att[2 * 64 * 64 * 128];       // [B,H,W,C]

__device__ __forceinline__ int nb_start(int i) {
    int s = i - 3;
    s = s < 0 ? 0 : s;
    return s > 57 ? 57 : s;   // L-K = 64-7
}

// ---- bf16 2-term split helpers ----------------------------------------------
__device__ __forceinline__ uint32_t bf16_split_pack(float x) {
    __nv_bfloat16 h = __float2bfloat16(x);
    float r = x - __bfloat162float(h);
    __nv_bfloat16 l = __float2bfloat16(r);
    return (uint32_t)__bfloat16_as_ushort(h) |
           ((uint32_t)__bfloat16_as_ushort(l) << 16);
}

__device__ __forceinline__ void mma_bf16(float* d, const uint32_t* a, const uint32_t* b) {
    asm("mma.sync.aligned.m16n8k16.row.col.f32.bf16.bf16.f32 "
        "{%0,%1,%2,%3}, {%4,%5,%6,%7}, {%8,%9}, {%0,%1,%2,%3};"
        : "+f"(d[0]), "+f"(d[1]), "+f"(d[2]), "+f"(d[3])
        : "r"(a[0]), "r"(a[1]), "r"(a[2]), "r"(a[3]), "r"(b[0]), "r"(b[1]));
}

// ---------------- kernel A: sinusoidal emb + silu + adaLN MLP -----------------
__global__ void adaln_kernel(const int* __restrict__ t,
                             const float* __restrict__ ln_w,
                             const float* __restrict__ ln_b) {
    __shared__ float s_silu[128];
    const int b = blockIdx.x;
    const int tid = threadIdx.x;
    const float tf = (float)t[b] * 40.0f;              // t/100*4000
    if (tid < 64) {
        float f = __expf(-(float)tid * (9.210340371976184f / 63.0f));
        float e = tf * f;
        float se = sinf(e), ce = cosf(e);
        s_silu[tid]      = se / (1.0f + __expf(-se));
        s_silu[tid + 64] = ce / (1.0f + __expf(-ce));
    }
    __syncthreads();
    const int j = tid;                                  // 0..255
    float acc = ln_b[j];
#pragma unroll 16
    for (int k = 0; k < 128; k++) acc += s_silu[k] * ln_w[k * 256 + j];
    g_ada[b * 256 + j] = acc;
}

// ---------------- kernel B: LayerNorm + modulate -> g_y -----------------------
__global__ void ln_kernel(const float* __restrict__ x) {
    const int tid = threadIdx.x;
    const int warp = tid >> 5, lane = tid & 31;
    const int row = blockIdx.x * 8 + warp;
    const int b = row >> 12;

    const float4 xv = *(const float4*)(x + row * 128 + lane * 4);
    float sum = xv.x + xv.y + xv.z + xv.w;
    float sq  = xv.x * xv.x + xv.y * xv.y + xv.z * xv.z + xv.w * xv.w;
#pragma unroll
    for (int o = 16; o; o >>= 1) {
        sum += __shfl_xor_sync(FULL, sum, o);
        sq  += __shfl_xor_sync(FULL, sq, o);
    }
    const float mean = sum * (1.0f / 128.0f);
    const float var  = sq * (1.0f / 128.0f) - mean * mean;
    const float rstd = rsqrtf(var + 1e-5f);

    const float4 sc = *(const float4*)(g_ada + b * 256 + lane * 4);
    const float4 sh = *(const float4*)(g_ada + b * 256 + 128 + lane * 4);
    float4 yv;
    yv.x = (xv.x - mean) * rstd * (1.0f + sc.x) + sh.x;
    yv.y = (xv.y - mean) * rstd * (1.0f + sc.y) + sh.y;
    yv.z = (xv.z - mean) * rstd * (1.0f + sc.z) + sh.z;
    yv.w = (xv.w - mean) * rstd * (1.0f + sc.w) + sh.w;
    *(float4*)(g_y + row * 128 + lane * 4) = yv;
}

// ---------------- kernel C: qkv GEMM (bf16x3 split tensor core) ---------------
// grid(128, 6), block(128) = 4 warps (2x2). tile 64x64, warp tile 32x32.
__global__ void __launch_bounds__(128)
qkv_gemm_tc(const float* __restrict__ W, const float* __restrict__ bias) {
    extern __shared__ uint32_t smem[];
    uint32_t* sa = smem;              // [64][132] packed bf16x2(hi,lo)
    uint32_t* sb = smem + 64 * 132;   // [128][72]

    const int tid = threadIdx.x;
    const int m0 = blockIdx.x * 64, n0 = blockIdx.y * 64;

    // stage A (split once)
#pragma unroll
    for (int r = 0; r < 16; r++) {
        const int id = tid + r * 128;
        const int row = id >> 5, j4 = id & 31;
        const float4 v = *(const float4*)(g_y + (m0 + row) * 128 + j4 * 4);
        uint32_t* p = sa + row * 132 + j4 * 4;
        p[0] = bf16_split_pack(v.x); p[1] = bf16_split_pack(v.y);
        p[2] = bf16_split_pack(v.z); p[3] = bf16_split_pack(v.w);
    }
    // stage B: W[k][n0+j], stride 384
#pragma unroll
    for (int r = 0; r < 16; r++) {
        const int id = tid + r * 128;
        const int kk = id >> 4, j4 = id & 15;
        const float4 v = *(const float4*)(W + kk * 384 + n0 + j4 * 4);
        uint32_t* p = sb + kk * 72 + j4 * 4;
        p[0] = bf16_split_pack(v.x); p[1] = bf16_split_pack(v.y);
        p[2] = bf16_split_pack(v.z); p[3] = bf16_split_pack(v.w);
    }
    __syncthreads();

    const int lane = tid & 31, warp = tid >> 5;
    const int wm = warp & 1, wn = warp >> 1;
    const int g = lane >> 2, tig = lane & 3;

    float d[2][4][4];
#pragma unroll
    for (int fm = 0; fm < 2; fm++)
#pragma unroll
        for (int fn = 0; fn < 4; fn++)
#pragma unroll
            for (int e = 0; e < 4; e++) d[fm][fn][e] = 0.0f;

#pragma unroll 4
    for (int k0 = 0; k0 < 128; k0 += 8) {
        uint32_t a[2][4];
#pragma unroll
        for (int fm = 0; fm < 2; fm++) {
            const int r = wm * 32 + fm * 16 + g;
            a[fm][0] = sa[(r    ) * 132 + k0 + tig];
            a[fm][1] = sa[(r + 8) * 132 + k0 + tig];
            a[fm][2] = sa[(r    ) * 132 + k0 + tig + 4];
            a[fm][3] = sa[(r + 8) * 132 + k0 + tig + 4];
        }
#pragma unroll
        for (int fn = 0; fn < 4; fn++) {
            const int c = wn * 32 + fn * 8 + g;
            const uint32_t p0 = sb[(k0 + tig    ) * 72 + c];
            const uint32_t p1 = sb[(k0 + tig + 4) * 72 + c];
            uint32_t bhh[2] = { __byte_perm(p0, p0, 0x1010),
                                __byte_perm(p1, p1, 0x1010) };
            uint32_t bl0[2] = { __byte_perm(p0, 0, 0x4432),
                                __byte_perm(p1, 0, 0x4432) };
#pragma unroll
            for (int fm = 0; fm < 2; fm++) {
                mma_bf16(d[fm][fn], a[fm], bhh);
                mma_bf16(d[fm][fn], a[fm], bl0);
            }
        }
    }

    // epilogue: scatter
    const float qscale = 0.17677669529663687f;   // 32^-0.5
#pragma unroll
    for (int fn = 0; fn < 4; fn++) {
        const int j0 = n0 + wn * 32 + fn * 8 + 2 * tig;
        const float bv0 = bias[j0], bv1 = bias[j0 + 1];
        const int which = j0 >> 7;
        const int rem = j0 & 127;
        const int nh = rem >> 5, dd = rem & 31;
#pragma unroll
        for (int fm = 0; fm < 2; fm++) {
#pragma unroll
            for (int half = 0; half < 2; half++) {
                const int row = m0 + wm * 32 + fm * 16 + g + half * 8;
                const int bb = row >> 12, hh = (row >> 6) & 63, ww = row & 63;
                const int idx = (((bb * 4 + nh) * 64 + hh) * 64 + ww) * 32 + dd;
                float v0 = d[fm][fn][half * 2 + 0] + bv0;
                float v1 = d[fm][fn][half * 2 + 1] + bv1;
                if (which == 0) {
                    v0 *= qscale; v1 *= qscale;
                    *(float2*)(g_q + idx) = make_float2(v0, v1);
                } else if (which == 1) {
                    *(float2*)(g_k + idx) = make_float2(v0, v1);
                } else {
                    *(float2*)(g_v + idx) = make_float2(v0, v1);
                }
            }
        }
    }
}

// ---------------- kernel D: 7x7 neighborhood attention, two-phase -------------
// grid(32 h-tiles, 8 bn), block(128) = 2 h-rows x 64 w. Thread-per-query.
// Phase 1: stage K (<=8 rows, 64KB), compute 49 raw scores into regs.
// Phase 2: re-use the same smem for V, softmax + accumulate.
// __launch_bounds__(128, 3): cap regs at 170 -> 3 blocks/SM (was 2 at 172 regs).
__global__ void __launch_bounds__(128, 3)
natten_kernel(const float* __restrict__ rpb) {
    extern __shared__ float smem_f[];
    float* skv = smem_f;              // 8*64*32 = 16384 floats = 64KB
    float* srpb = smem_f + 16384;     // 169

    const int tid = threadIdx.x;
    const int h0 = blockIdx.x * 2;
    const int bn = blockIdx.y;
    const int b = bn >> 2, n = bn & 3;
    const int base = bn * (64 * 64 * 32);

    const int hs0 = nb_start(h0);
    const int nrows = nb_start(h0 + 1) + 6 - hs0 + 1;   // 7 or 8
    const int nchunks = nrows * 512;                     // rows*64*8 float4s

    // ---- phase 1: stage K ----
    for (int i = tid; i < nchunks; i += 128) {
        const int a = i >> 9;
        const int rem = i & 511;
        const int w = rem >> 3, j = rem & 7;
        ((float4*)skv)[(a * 64 + w) * 8 + (j ^ (w & 7))] =
            *(const float4*)(g_k + base + (hs0 + a) * 2048 + w * 32 + j * 4);
    }
    for (int i = tid; i < 169; i += 128) srpb[i] = rpb[n * 169 + i];
    __syncthreads();

    const int ih = tid >> 6;
    const int w = tid & 63;
    const int h = h0 + ih;
    const int ws = nb_start(w);
    const int hs_q = nb_start(h);
    const int arow0 = hs_q - hs0;
    const int rbase = (hs_q - h + 6) * 13 + (ws - w + 6);

    float4 q4[8];
    {
        const int qoff = base + h * 2048 + w * 32;
#pragma unroll
        for (int j = 0; j < 8; j++) q4[j] = *(const float4*)(g_q + qoff + 4 * j);
    }

    float s[49];
#pragma unroll
    for (int a = 0; a < 7; a++) {
        const int row = arow0 + a;
#pragma unroll
        for (int c = 0; c < 7; c++) {
            const int col = ws + c;
            const float4* kp = ((const float4*)skv) + (row * 64 + col) * 8;
            const int sw = col & 7;
            float p0 = 0.f, p1 = 0.f, p2 = 0.f, p3 = 0.f;
#pragma unroll
            for (int j = 0; j < 8; j++) {
                const float4 kv = kp[j ^ sw];
                p0 += q4[j].x * kv.x;
                p1 += q4[j].y * kv.y;
                p2 += q4[j].z * kv.z;
                p3 += q4[j].w * kv.w;
            }
            s[a * 7 + c] = (p0 + p1) + (p2 + p3) + srpb[rbase + a * 13 + c];
        }
    }

    float m = s[0];
#pragma unroll
    for (int i = 1; i < 49; i++) m = fmaxf(m, s[i]);
    float l = 0.f;
#pragma unroll
    for (int i = 0; i < 49; i++) { s[i] = __expf(s[i] - m); l += s[i]; }
    const float inv = 1.0f / l;

    __syncthreads();   // everyone done reading K

    // ---- phase 2: stage V into the same buffer ----
    for (int i = tid; i < nchunks; i += 128) {
        const int a = i >> 9;
        const int rem = i & 511;
        const int w_ = rem >> 3, j = rem & 7;
        ((float4*)skv)[(a * 64 + w_) * 8 + (j ^ (w_ & 7))] =
            *(const float4*)(g_v + base + (hs0 + a) * 2048 + w_ * 32 + j * 4);
    }
    __syncthreads();

    float4 acc4[8];
#pragma unroll
    for (int j = 0; j < 8; j++) acc4[j] = make_float4(0.f, 0.f, 0.f, 0.f);

#pragma unroll
    for (int a = 0; a < 7; a++) {
        const int row = arow0 + a;
        const float4* vp = ((const float4*)skv) + (row * 64 + ws) * 8;
#pragma unroll
        for (int j = 0; j < 8; j++) {
            float4 av = acc4[j];
#pragma unroll
            for (int c = 0; c < 7; c++) {
                const int col = ws + c;
                const float4 vv = vp[c * 8 + (j ^ (col & 7))];
                const float p = s[a * 7 + c];
                av.x += p * vv.x;
                av.y += p * vv.y;
                av.z += p * vv.z;
                av.w += p * vv.w;
            }
            acc4[j] = av;
        }
    }

    const int ob = ((b * 64 + h) * 64 + w) * 128 + n * 32;
#pragma unroll
    for (int j = 0; j < 8; j++) {
        float4 o = acc4[j];
        o.x *= inv; o.y *= inv; o.z *= inv; o.w *= inv;
        *(float4*)(g_att + ob + 4 * j) = o;
    }
}

// ---------------- kernel E: proj GEMM (bf16x3 split tensor core) --------------
__global__ void __launch_bounds__(128)
proj_gemm_tc(const float* __restrict__ W, const float* __restrict__ bias,
             float* __restrict__ out) {
    extern __shared__ uint32_t smem[];
    uint32_t* sa = smem;              // [64][132]
    uint32_t* sb = smem + 64 * 132;   // [128][72]

    const int tid = threadIdx.x;
    const int m0 = blockIdx.x * 64, n0 = blockIdx.y * 64;

#pragma unroll
    for (int r = 0; r < 16; r++) {
        const int id = tid + r * 128;
        const int row = id >> 5, j4 = id & 31;
        const float4 v = *(const float4*)(g_att + (m0 + row) * 128 + j4 * 4);
        uint32_t* p = sa + row * 132 + j4 * 4;
        p[0] = bf16_split_pack(v.x); p[1] = bf16_split_pack(v.y);
        p[2] = bf16_split_pack(v.z); p[3] = bf16_split_pack(v.w);
    }
#pragma unroll
    for (int r = 0; r < 16; r++) {
        const int id = tid + r * 128;
        const int kk = id >> 4, j4 = id & 15;
        const float4 v = *(const float4*)(W + kk * 128 + n0 + j4 * 4);
        uint32_t* p = sb + kk * 72 + j4 * 4;
        p[0] = bf16_split_pack(v.x); p[1] = bf16_split_pack(v.y);
        p[2] = bf16_split_pack(v.z); p[3] = bf16_split_pack(v.w);
    }
    __syncthreads();

    const int lane = tid & 31, warp = tid >> 5;
    const int wm = warp & 1, wn = warp >> 1;
    const int g = lane >> 2, tig = lane & 3;

    float d[2][4][4];
#pragma unroll
    for (int fm = 0; fm < 2; fm++)
#pragma unroll
        for (int fn = 0; fn < 4; fn++)
#pragma unroll
            for (int e = 0; e < 4; e++) d[fm][fn][e] = 0.0f;

#pragma unroll 4
    for (int k0 = 0; k0 < 128; k0 += 8) {
        uint32_t a[2][4];
#pragma unroll
        for (int fm = 0; fm < 2; fm++) {
            const int r = wm * 32 + fm * 16 + g;
            a[fm][0] = sa[(r    ) * 132 + k0 + tig];
            a[fm][1] = sa[(r + 8) * 132 + k0 + tig];
            a[fm][2] = sa[(r    ) * 132 + k0 + tig + 4];
            a[fm][3] = sa[(r + 8) * 132 + k0 + tig + 4];
        }
#pragma unroll
        for (int fn = 0; fn < 4; fn++) {
            const int c = wn * 32 + fn * 8 + g;
            const uint32_t p0 = sb[(k0 + tig    ) * 72 + c];
            const uint32_t p1 = sb[(k0 + tig + 4) * 72 + c];
            uint32_t bhh[2] = { __byte_perm(p0, p0, 0x1010),
                                __byte_perm(p1, p1, 0x1010) };
            uint32_t bl0[2] = { __byte_perm(p0, 0, 0x4432),
                                __byte_perm(p1, 0, 0x4432) };
#pragma unroll
            for (int fm = 0; fm < 2; fm++) {
                mma_bf16(d[fm][fn], a[fm], bhh);
                mma_bf16(d[fm][fn], a[fm], bl0);
            }
        }
    }

#pragma unroll
    for (int fn = 0; fn < 4; fn++) {
        const int j0 = n0 + wn * 32 + fn * 8 + 2 * tig;
        const float bv0 = bias[j0], bv1 = bias[j0 + 1];
#pragma unroll
        for (int fm = 0; fm < 2; fm++) {
#pragma unroll
            for (int half = 0; half < 2; half++) {
                const int row = m0 + wm * 32 + fm * 16 + g + half * 8;
                float v0 = d[fm][fn][half * 2 + 0] + bv0;
                float v1 = d[fm][fn][half * 2 + 1] + bv1;
                *(float2*)(out + row * 128 + j0) = make_float2(v0, v1);
            }
        }
    }
}

// ---------------- launch ------------------------------------------------------
extern "C" void kernel_launch(void* const* d_in, const int* in_sizes, int n_in,
                              void* d_out, int out_size) {
    const float* x      = (const float*)d_in[0];
    // d_in[1] = cond (unused)
    const int*   t      = (const int*)d_in[2];
    const float* ln_w   = (const float*)d_in[3];
    const float* ln_b   = (const float*)d_in[4];
    const float* qkv_w  = (const float*)d_in[5];
    const float* qkv_b  = (const float*)d_in[6];
    const float* rpb    = (const float*)d_in[7];
    const float* proj_w = (const float*)d_in[8];
    const float* proj_b = (const float*)d_in[9];
    float* out = (float*)d_out;

    const int gemm_smem = (64 * 132 + 128 * 72) * 4;   // 70,656 B
    const int natten_smem = (16384 + 176) * 4;         // 66,240 B
    cudaFuncSetAttribute(qkv_gemm_tc,
                         cudaFuncAttributeMaxDynamicSharedMemorySize, gemm_smem);
    cudaFuncSetAttribute(proj_gemm_tc,
                         cudaFuncAttributeMaxDynamicSharedMemorySize, gemm_smem);
    cudaFuncSetAttribute(natten_kernel,
                         cudaFuncAttributeMaxDynamicSharedMemorySize, natten_smem);

    adaln_kernel<<<2, 256>>>(t, ln_w, ln_b);
    ln_kernel<<<1024, 256>>>(x);
    qkv_gemm_tc<<<dim3(128, 6), 128, gemm_smem>>>(qkv_w, qkv_b);
    natten_kernel<<<dim3(32, 8), 128, natten_smem>>>(rpb);
    proj_gemm_tc<<<dim3(128, 2), 128, gemm_smem>>>(proj_w, proj_b, out);
}